// round 15
// baseline (speedup 1.0000x reference)
#include <cuda_runtime.h>
#include <cuda_bf16.h>

// ---------------------------------------------------------------------------
// TrajectoryEncoder fused kernel (fp32, FFMA2 packed math).
// One CTA per polyline (B*P = 8192 CTAs, 256 threads). All activations live in
// shared memory; weights are streamed from L2 through padded/transposed smem
// tiles. Layers:
//   L0 pre0  : (20x32)  @ (256x32)^T  * (g*BN_INV) + b, relu
//   L1 pre1  : (20x256) @ (256x256)^T ...
//   L2 pre2  : (20x256) @ (256x256)^T + bias, * mask          -> x
//   pooled   : max over 20 rows of x
//   L3 mlp0  : (20x512 = [x | pooled]) @ (256x512)^T, relu
//   L4 mlp1  : (20x256) @ (256x256)^T, relu
//   L5 mlp2  : (20x256) @ (256x256)^T + bias, * mask          -> x2
//   buf      : max over 20 rows of x2
//   out0     : (1x256) @ (256x256)^T + b, relu
//   out1     : (1x256) @ (256x256)^T + b, * valid  -> output (B,P,256)
// ---------------------------------------------------------------------------

#define NPTS   20      // points per polyline
#define CIN    32      // input channels
#define HD     256     // hidden dim == OUT
#define KT     32      // K-tile width staged per step
#define WPAD   257     // padded row stride of transposed weight tile
#define NPOLY  8192    // B*P
#define NTHR   256

__device__ int g_mask_mode;   // 0=u8, 1=i32, 2=f32, 3=bf16

// ---------------- packed fp32x2 helpers (FFMA2) ----------------------------
static __device__ __forceinline__ unsigned long long pack2(float a, float b) {
    unsigned long long r;
    asm("mov.b64 %0, {%1, %2};" : "=l"(r) : "f"(a), "f"(b));
    return r;
}
static __device__ __forceinline__ unsigned long long fma2(
    unsigned long long a, unsigned long long b, unsigned long long c) {
    unsigned long long d;
    asm("fma.rn.f32x2 %0, %1, %2, %3;" : "=l"(d) : "l"(a), "l"(b), "l"(c));
    return d;
}
static __device__ __forceinline__ float2 unpack2(unsigned long long v) {
    float lo, hi;
    asm("mov.b64 {%0, %1}, %2;" : "=f"(lo), "=f"(hi) : "l"(v));
    return make_float2(lo, hi);
}

// ---------------- shared memory layout --------------------------------------
struct __align__(16) Smem {
    float Wt[KT][WPAD];        // transposed weight tile: Wt[k][j], pad 257
    float in0[NPTS][CIN];      // raw polyline points
    float actA[NPTS][HD];      // activation ping
    float actB[NPTS][HD];      // activation pong
    float pooled[HD];          // max-pool after pre stage
    float bufv[HD];            // max-pool after mlp stage
    float vec[HD];             // out-stage intermediate
    float maskf[NPTS];
    float validf;
};

// ---------------- GEMM core --------------------------------------------------
// Thread `tid` computes output column `tid` for NR rows.
// Input row n, element k comes from srcA (row-stride rsA) for k < KA, else
// from srcB (row-stride rsB) at offset k - KA.  Partial sums kept as packed
// fp32x2 (even/odd k lanes), reduced at the end.
template <int NR>
static __device__ __forceinline__ void gemm_block(
    Smem& s,
    const float* __restrict__ Wg, int K,        // Wg: [HD x K] row-major
    const float* srcA, int rsA, int KA,
    const float* srcB, int rsB,
    float* accf)
{
    const int tid  = threadIdx.x;
    const int warp = tid >> 5;
    const int lane = tid & 31;

    unsigned long long acc[NR];
#pragma unroll
    for (int n = 0; n < NR; n++) acc[n] = 0ULL;

    for (int k0 = 0; k0 < K; k0 += KT) {
        // Stage transposed tile: global read coalesced over k, smem write
        // conflict-free (bank = (lane + j) & 31).
#pragma unroll
        for (int it = 0; it < 32; it++) {
            int j = it * 8 + warp;                      // 0..255
            s.Wt[lane][j] = Wg[(size_t)j * K + (k0 + lane)];
        }
        __syncthreads();

        const float* src;
        int rs;
        if (k0 < KA) { src = srcA + k0;        rs = rsA; }
        else         { src = srcB + (k0 - KA); rs = rsB; }

#pragma unroll
        for (int kq = 0; kq < KT / 4; kq++) {
            // per-thread column reads: bank = (tid + 4kq) & 31, conflict-free
            unsigned long long wA = pack2(s.Wt[4 * kq + 0][tid], s.Wt[4 * kq + 1][tid]);
            unsigned long long wB = pack2(s.Wt[4 * kq + 2][tid], s.Wt[4 * kq + 3][tid]);
#pragma unroll
            for (int n = 0; n < NR; n++) {
                const float* p = src + n * rs + 4 * kq;  // 16B aligned
                ulonglong2 iv = *reinterpret_cast<const ulonglong2*>(p);
                acc[n] = fma2(wA, iv.x, acc[n]);
                acc[n] = fma2(wB, iv.y, acc[n]);
            }
        }
        __syncthreads();
    }

#pragma unroll
    for (int n = 0; n < NR; n++) {
        float2 f = unpack2(acc[n]);
        accf[n] = f.x + f.y;
    }
}

// ---------------- mask dtype sniffing ---------------------------------------
// The mask is a jax bool array; the harness may hand it to us as uint8, int32,
// float32 or bfloat16.  Classify from the byte pattern of the first `nelem`
// bytes (a safe lower bound on the buffer size for every candidate dtype).
__global__ void detect_mask_mode_kernel(const unsigned char* __restrict__ m, int nelem)
{
    __shared__ int nz[4];
    __shared__ int mx;
    int t = threadIdx.x;
    if (t < 4) nz[t] = 0;
    if (t == 0) mx = 0;
    __syncthreads();

    int l0 = 0, l1 = 0, l2 = 0, l3 = 0, lm = 0;
    for (int i = t; i < nelem; i += blockDim.x) {
        int v = m[i];
        if (v) {
            int o = i & 3;
            l0 |= (o == 0); l1 |= (o == 1); l2 |= (o == 2); l3 |= (o == 3);
            if (v > lm) lm = v;
        }
    }
    if (l0) atomicOr(&nz[0], 1);
    if (l1) atomicOr(&nz[1], 1);
    if (l2) atomicOr(&nz[2], 1);
    if (l3) atomicOr(&nz[3], 1);
    atomicMax(&mx, lm);
    __syncthreads();

    if (t == 0) {
        int mode;
        if (nz[1])                 mode = (mx > 1) ? 3 : 0;  // bf16 (0x3F80) vs u8 0/1
        else if (nz[2] || nz[3])   mode = 2;                 // f32 1.0f = 00 00 80 3F
        else if (nz[0])            mode = (mx > 1) ? 0 : 1;  // i32 0/1
        else                       mode = 0;                 // all-zero: any works
        g_mask_mode = mode;
    }
}

// ---------------- main fused kernel ------------------------------------------
__global__ void __launch_bounds__(NTHR, 2)
traj_encoder_kernel(
    const float* __restrict__ poly,
    const void*  __restrict__ maskp,
    const float* __restrict__ pre_w0,  const float* __restrict__ pre_g0,  const float* __restrict__ pre_b0,
    const float* __restrict__ pre_w1,  const float* __restrict__ pre_g1,  const float* __restrict__ pre_b1,
    const float* __restrict__ pre_w2,  const float* __restrict__ pre_bias2,
    const float* __restrict__ mlp_w0,  const float* __restrict__ mlp_g0,  const float* __restrict__ mlp_b0,
    const float* __restrict__ mlp_w1,  const float* __restrict__ mlp_g1,  const float* __restrict__ mlp_b1,
    const float* __restrict__ mlp_w2,  const float* __restrict__ mlp_bias2,
    const float* __restrict__ out_w0,  const float* __restrict__ out_b0,
    const float* __restrict__ out_w1,  const float* __restrict__ out_b1,
    float* __restrict__ outp)
{
    extern __shared__ unsigned char smem_raw[];
    Smem& s = *reinterpret_cast<Smem*>(smem_raw);

    const int tid = threadIdx.x;
    const int pl  = blockIdx.x;
    const float BN_INV = 0.99999500003749969f;   // 1/sqrt(1+1e-5)
    const int mmode = g_mask_mode;

    // ---- load points + mask --------------------------------------------------
    const float* pin = poly + (size_t)pl * (NPTS * CIN);
    for (int i = tid; i < NPTS * CIN; i += NTHR)
        (&s.in0[0][0])[i] = pin[i];

    if (tid < NPTS) {
        const int gi = pl * NPTS + tid;
        bool mv;
        switch (mmode) {
            case 1:  mv = ((const int*)maskp)[gi] != 0;                                  break;
            case 2:  mv = ((const float*)maskp)[gi] != 0.0f;                             break;
            case 3:  mv = __bfloat162float(((const __nv_bfloat16*)maskp)[gi]) != 0.0f;   break;
            default: mv = ((const unsigned char*)maskp)[gi] != 0;                        break;
        }
        s.maskf[tid] = mv ? 1.0f : 0.0f;
    }
    __syncthreads();
    if (tid == 0) {
        float v = 0.0f;
        for (int n = 0; n < NPTS; n++) v = fmaxf(v, s.maskf[n]);
        s.validf = v;
    }
    __syncthreads();

    float accf[NPTS];

    // ---- L0: pre0 (K=32) -> actA, relu ----------------------------------------
    gemm_block<NPTS>(s, pre_w0, CIN, &s.in0[0][0], CIN, CIN, &s.in0[0][0], CIN, accf);
    {
        const float sc = pre_g0[tid] * BN_INV, bi = pre_b0[tid];
#pragma unroll
        for (int n = 0; n < NPTS; n++)
            s.actA[n][tid] = fmaxf(fmaf(accf[n], sc, bi), 0.0f);
    }
    __syncthreads();

    // ---- L1: pre1 (K=256) actA -> actB, relu -----------------------------------
    gemm_block<NPTS>(s, pre_w1, HD, &s.actA[0][0], HD, HD, &s.actA[0][0], HD, accf);
    {
        const float sc = pre_g1[tid] * BN_INV, bi = pre_b1[tid];
#pragma unroll
        for (int n = 0; n < NPTS; n++)
            s.actB[n][tid] = fmaxf(fmaf(accf[n], sc, bi), 0.0f);
    }
    __syncthreads();

    // ---- L2: pre2 (K=256) actB -> actA = x, +bias, *mask ------------------------
    gemm_block<NPTS>(s, pre_w2, HD, &s.actB[0][0], HD, HD, &s.actB[0][0], HD, accf);
    {
        const float bi = pre_bias2[tid];
#pragma unroll
        for (int n = 0; n < NPTS; n++)
            s.actA[n][tid] = (accf[n] + bi) * s.maskf[n];
    }
    __syncthreads();

    // ---- pooled = max over rows of x -------------------------------------------
    {
        float mv = s.actA[0][tid];
#pragma unroll
        for (int n = 1; n < NPTS; n++) mv = fmaxf(mv, s.actA[n][tid]);
        s.pooled[tid] = mv;
    }
    __syncthreads();

    // ---- L3: mlp0 (K=512 = [x | pooled]) -> actB, relu ---------------------------
    gemm_block<NPTS>(s, mlp_w0, 2 * HD, &s.actA[0][0], HD, HD, &s.pooled[0], 0, accf);
    {
        const float sc = mlp_g0[tid] * BN_INV, bi = mlp_b0[tid];
#pragma unroll
        for (int n = 0; n < NPTS; n++)
            s.actB[n][tid] = fmaxf(fmaf(accf[n], sc, bi), 0.0f);
    }
    __syncthreads();

    // ---- L4: mlp1 (K=256) actB -> actA, relu -------------------------------------
    gemm_block<NPTS>(s, mlp_w1, HD, &s.actB[0][0], HD, HD, &s.actB[0][0], HD, accf);
    {
        const float sc = mlp_g1[tid] * BN_INV, bi = mlp_b1[tid];
#pragma unroll
        for (int n = 0; n < NPTS; n++)
            s.actA[n][tid] = fmaxf(fmaf(accf[n], sc, bi), 0.0f);
    }
    __syncthreads();

    // ---- L5: mlp2 (K=256) actA -> actB = x2, +bias, *mask --------------------------
    gemm_block<NPTS>(s, mlp_w2, HD, &s.actA[0][0], HD, HD, &s.actA[0][0], HD, accf);
    {
        const float bi = mlp_bias2[tid];
#pragma unroll
        for (int n = 0; n < NPTS; n++)
            s.actB[n][tid] = (accf[n] + bi) * s.maskf[n];
    }
    __syncthreads();

    // ---- buf = max over rows of x2 --------------------------------------------------
    {
        float mv = s.actB[0][tid];
#pragma unroll
        for (int n = 1; n < NPTS; n++) mv = fmaxf(mv, s.actB[n][tid]);
        s.bufv[tid] = mv;
    }
    __syncthreads();

    // ---- out0: vec = relu(buf @ W0^T + b0) -------------------------------------------
    float yv;
    gemm_block<1>(s, out_w0, HD, &s.bufv[0], 0, HD, &s.bufv[0], 0, &yv);
    s.vec[tid] = fmaxf(yv + out_b0[tid], 0.0f);
    __syncthreads();

    // ---- out1: y = (vec @ W1^T + b1) * valid -------------------------------------------
    gemm_block<1>(s, out_w1, HD, &s.vec[0], 0, HD, &s.vec[0], 0, &yv);
    outp[(size_t)pl * HD + tid] = (yv + out_b1[tid]) * s.validf;
}

// ---------------- launch ------------------------------------------------------
extern "C" void kernel_launch(void* const* d_in, const int* in_sizes, int n_in,
                              void* d_out, int out_size)
{
    const float* poly = (const float*)d_in[0];
    const void*  mask = d_in[1];

    detect_mask_mode_kernel<<<1, 256>>>((const unsigned char*)mask, in_sizes[1]);

    const int smem_bytes = (int)sizeof(Smem);
    cudaFuncSetAttribute(traj_encoder_kernel,
                         cudaFuncAttributeMaxDynamicSharedMemorySize, smem_bytes);

    traj_encoder_kernel<<<NPOLY, NTHR, smem_bytes>>>(
        poly, mask,
        (const float*)d_in[2],  (const float*)d_in[3],  (const float*)d_in[4],
        (const float*)d_in[5],  (const float*)d_in[6],  (const float*)d_in[7],
        (const float*)d_in[8],  (const float*)d_in[9],
        (const float*)d_in[10], (const float*)d_in[11], (const float*)d_in[12],
        (const float*)d_in[13], (const float*)d_in[14], (const float*)d_in[15],
        (const float*)d_in[16], (const float*)d_in[17],
        (const float*)d_in[18], (const float*)d_in[19],
        (const float*)d_in[20], (const float*)d_in[21],
        (float*)d_out);
}

// round 16
// speedup vs baseline: 1.4277x; 1.4277x over previous
#include <cuda_runtime.h>
#include <cuda_bf16.h>

// ---------------------------------------------------------------------------
// TrajectoryEncoder fused kernel, v2.
// One CTA per polyline (8192 CTAs x 256 threads). fp32 math via packed
// fma.rn.f32x2. Register blocking: each thread computes 4 strided columns
// (j = cg + 64c) x 5 rows. Weight tiles staged to smem with 36-float row
// stride (conflict-free STS.128 and strided LDS.128). The pooled half of
// mlp0 is factored out as a per-polyline vector GEMM (pvec) and added in
// the epilogue (removes ~16% of FLOPs).
// ---------------------------------------------------------------------------

#define NPTS   20
#define CIN    32
#define HD     256
#define KT     32          // k-tile width
#define WSTR   36          // padded tile row stride (floats), 9 x 16B units
#define NPOLY  8192
#define NTHR   256

__device__ int g_mask_mode;   // 0=u8, 1=i32, 2=f32, 3=bf16

typedef unsigned long long ull;

// ---------------- packed fp32x2 helpers -------------------------------------
static __device__ __forceinline__ ull fma2(ull a, ull b, ull c) {
    ull d;
    asm("fma.rn.f32x2 %0, %1, %2, %3;" : "=l"(d) : "l"(a), "l"(b), "l"(c));
    return d;
}
static __device__ __forceinline__ float2 unpack2(ull v) {
    float lo, hi;
    asm("mov.b64 {%0, %1}, %2;" : "=f"(lo), "=f"(hi) : "l"(v));
    return make_float2(lo, hi);
}
static __device__ __forceinline__ float hsum(ull v) {
    float2 f = unpack2(v);
    return f.x + f.y;
}

// ---------------- shared memory layout --------------------------------------
struct __align__(16) Smem {
    float Wt2[HD * WSTR];      // weight tile, row j at Wt2[j*36 .. +31]
    float in0[NPTS][CIN];
    float actA[NPTS][HD];
    float actB[NPTS][HD];
    float pooled[HD];
    float pvec[HD];
    float bufv[HD];
    float vec[HD];
    float maskf[NPTS];
    float validf;
};

// ---------------- weight tile staging ----------------------------------------
// Loads HD x KT tile starting at column k0 of Wg (row stride ldw floats).
// Global: coalesced float4 reads. Smem: conflict-free STS.128 (stride 9 units).
static __device__ __forceinline__ void stage_tile(
    float* __restrict__ Wt2, const float* __restrict__ Wg, int ldw, int k0)
{
    const int tid = threadIdx.x;
    const int jr  = tid >> 3;          // 0..31
    const int kk  = (tid & 7) * 4;     // 0..28
#pragma unroll
    for (int it = 0; it < 8; it++) {
        int j = it * 32 + jr;
        float4 v = *reinterpret_cast<const float4*>(Wg + (size_t)j * ldw + k0 + kk);
        *reinterpret_cast<float4*>(Wt2 + j * WSTR + kk) = v;
    }
}

// ---------------- main GEMM: 4 cols x 5 rows per thread -----------------------
// acc[c][n] accumulates (packed over k pairs) for column cg+64c, row n0+n.
// src: activation rows, row stride rs floats. NT tiles of KT.
template <int NT>
static __device__ __forceinline__ void gemm20(
    Smem& s, const float* __restrict__ Wg, int ldw, int k0off,
    const float* __restrict__ src, int rs,
    ull acc[4][5], int cg, int n0)
{
#pragma unroll 1
    for (int t = 0; t < NT; t++) {
        __syncthreads();
        stage_tile(s.Wt2, Wg, ldw, k0off + t * KT);
        __syncthreads();
        const float* sp = src + t * KT;
#pragma unroll
        for (int kq = 0; kq < KT / 4; kq++) {
            // weights: 4 strided columns, 16B each (k..k+3), conflict-free
            ulonglong2 w0 = *reinterpret_cast<const ulonglong2*>(&s.Wt2[(cg      ) * WSTR + 4 * kq]);
            ulonglong2 w1 = *reinterpret_cast<const ulonglong2*>(&s.Wt2[(cg +  64) * WSTR + 4 * kq]);
            ulonglong2 w2 = *reinterpret_cast<const ulonglong2*>(&s.Wt2[(cg + 128) * WSTR + 4 * kq]);
            ulonglong2 w3 = *reinterpret_cast<const ulonglong2*>(&s.Wt2[(cg + 192) * WSTR + 4 * kq]);
#pragma unroll
            for (int n = 0; n < 5; n++) {
                ulonglong2 iv = *reinterpret_cast<const ulonglong2*>(sp + (n0 + n) * rs + 4 * kq);
                acc[0][n] = fma2(w0.x, iv.x, acc[0][n]);
                acc[0][n] = fma2(w0.y, iv.y, acc[0][n]);
                acc[1][n] = fma2(w1.x, iv.x, acc[1][n]);
                acc[1][n] = fma2(w1.y, iv.y, acc[1][n]);
                acc[2][n] = fma2(w2.x, iv.x, acc[2][n]);
                acc[2][n] = fma2(w2.y, iv.y, acc[2][n]);
                acc[3][n] = fma2(w3.x, iv.x, acc[3][n]);
                acc[3][n] = fma2(w3.y, iv.y, acc[3][n]);
            }
        }
    }
}

// ---------------- vector GEMM: 1 row, thread tid = column tid ------------------
// y[tid] = sum_k Wg[tid*ldw + k0off + k] * src[k],  K = 256.
static __device__ __forceinline__ float gemmvec(
    Smem& s, const float* __restrict__ Wg, int ldw, int k0off,
    const float* __restrict__ src)
{
    const int tid = threadIdx.x;
    ull a0 = 0ULL, a1 = 0ULL;
#pragma unroll 1
    for (int t = 0; t < 8; t++) {
        __syncthreads();
        stage_tile(s.Wt2, Wg, ldw, k0off + t * KT);
        __syncthreads();
        const float* sp = src + t * KT;
#pragma unroll
        for (int kq = 0; kq < KT / 4; kq++) {
            ulonglong2 w  = *reinterpret_cast<const ulonglong2*>(&s.Wt2[tid * WSTR + 4 * kq]);
            ulonglong2 iv = *reinterpret_cast<const ulonglong2*>(sp + 4 * kq);
            a0 = fma2(w.x, iv.x, a0);
            a1 = fma2(w.y, iv.y, a1);
        }
    }
    return hsum(a0) + hsum(a1);
}

// ---------------- mask dtype sniffing -----------------------------------------
__global__ void detect_mask_mode_kernel(const unsigned char* __restrict__ m, int nelem)
{
    __shared__ int nz[4];
    __shared__ int mx;
    int t = threadIdx.x;
    if (t < 4) nz[t] = 0;
    if (t == 0) mx = 0;
    __syncthreads();

    int l0 = 0, l1 = 0, l2 = 0, l3 = 0, lm = 0;
    for (int i = t; i < nelem; i += blockDim.x) {
        int v = m[i];
        if (v) {
            int o = i & 3;
            l0 |= (o == 0); l1 |= (o == 1); l2 |= (o == 2); l3 |= (o == 3);
            if (v > lm) lm = v;
        }
    }
    if (l0) atomicOr(&nz[0], 1);
    if (l1) atomicOr(&nz[1], 1);
    if (l2) atomicOr(&nz[2], 1);
    if (l3) atomicOr(&nz[3], 1);
    atomicMax(&mx, lm);
    __syncthreads();

    if (t == 0) {
        int mode;
        if (nz[1])               mode = (mx > 1) ? 3 : 0;   // bf16 vs u8 0/1
        else if (nz[2] || nz[3]) mode = 2;                  // f32
        else if (nz[0])          mode = (mx > 1) ? 0 : 1;   // u8 vs i32
        else                     mode = 0;
        g_mask_mode = mode;
    }
}

// ---------------- main fused kernel --------------------------------------------
__global__ void __launch_bounds__(NTHR, 2)
traj_encoder_kernel(
    const float* __restrict__ poly,
    const void*  __restrict__ maskp,
    const float* __restrict__ pre_w0,  const float* __restrict__ pre_g0,  const float* __restrict__ pre_b0,
    const float* __restrict__ pre_w1,  const float* __restrict__ pre_g1,  const float* __restrict__ pre_b1,
    const float* __restrict__ pre_w2,  const float* __restrict__ pre_bias2,
    const float* __restrict__ mlp_w0,  const float* __restrict__ mlp_g0,  const float* __restrict__ mlp_b0,
    const float* __restrict__ mlp_w1,  const float* __restrict__ mlp_g1,  const float* __restrict__ mlp_b1,
    const float* __restrict__ mlp_w2,  const float* __restrict__ mlp_bias2,
    const float* __restrict__ out_w0,  const float* __restrict__ out_b0,
    const float* __restrict__ out_w1,  const float* __restrict__ out_b1,
    float* __restrict__ outp)
{
    extern __shared__ unsigned char smem_raw[];
    Smem& s = *reinterpret_cast<Smem*>(smem_raw);

    const int tid = threadIdx.x;
    const int cg  = tid & 63;          // column group: cols cg + 64c
    const int n0  = (tid >> 6) * 5;    // row group: rows n0..n0+4
    const int pl  = blockIdx.x;
    const float BN_INV = 0.99999500003749969f;   // 1/sqrt(1+1e-5)
    const int mmode = g_mask_mode;

    // ---- load points + mask ---------------------------------------------------
    const float* pin = poly + (size_t)pl * (NPTS * CIN);
    for (int i = tid; i < NPTS * CIN; i += NTHR)
        (&s.in0[0][0])[i] = pin[i];

    if (tid < NPTS) {
        const int gi = pl * NPTS + tid;
        bool mv;
        switch (mmode) {
            case 1:  mv = ((const int*)maskp)[gi] != 0;                                  break;
            case 2:  mv = ((const float*)maskp)[gi] != 0.0f;                             break;
            case 3:  mv = __bfloat162float(((const __nv_bfloat16*)maskp)[gi]) != 0.0f;   break;
            default: mv = ((const unsigned char*)maskp)[gi] != 0;                        break;
        }
        s.maskf[tid] = mv ? 1.0f : 0.0f;
    }
    __syncthreads();
    if (tid == 0) {
        float v = 0.0f;
        for (int n = 0; n < NPTS; n++) v = fmaxf(v, s.maskf[n]);
        s.validf = v;
    }
    // (gemm20's internal first __syncthreads covers visibility)

    ull acc[4][5];

    // ================= L0: pre0 (K=32) -> actA, BN+relu =========================
#pragma unroll
    for (int c = 0; c < 4; c++)
#pragma unroll
        for (int n = 0; n < 5; n++) acc[c][n] = 0ULL;
    gemm20<1>(s, pre_w0, CIN, 0, &s.in0[0][0], CIN, acc, cg, n0);
#pragma unroll
    for (int c = 0; c < 4; c++) {
        int j = cg + 64 * c;
        float sc = pre_g0[j] * BN_INV, bi = pre_b0[j];
#pragma unroll
        for (int n = 0; n < 5; n++)
            s.actA[n0 + n][j] = fmaxf(fmaf(hsum(acc[c][n]), sc, bi), 0.0f);
    }

    // ================= L1: pre1 (K=256) actA -> actB, BN+relu ===================
#pragma unroll
    for (int c = 0; c < 4; c++)
#pragma unroll
        for (int n = 0; n < 5; n++) acc[c][n] = 0ULL;
    gemm20<8>(s, pre_w1, HD, 0, &s.actA[0][0], HD, acc, cg, n0);
#pragma unroll
    for (int c = 0; c < 4; c++) {
        int j = cg + 64 * c;
        float sc = pre_g1[j] * BN_INV, bi = pre_b1[j];
#pragma unroll
        for (int n = 0; n < 5; n++)
            s.actB[n0 + n][j] = fmaxf(fmaf(hsum(acc[c][n]), sc, bi), 0.0f);
    }

    // ================= L2: pre2 (K=256) actB -> actA, +bias, *mask ==============
#pragma unroll
    for (int c = 0; c < 4; c++)
#pragma unroll
        for (int n = 0; n < 5; n++) acc[c][n] = 0ULL;
    gemm20<8>(s, pre_w2, HD, 0, &s.actB[0][0], HD, acc, cg, n0);
#pragma unroll
    for (int c = 0; c < 4; c++) {
        int j = cg + 64 * c;
        float bi = pre_bias2[j];
#pragma unroll
        for (int n = 0; n < 5; n++)
            s.actA[n0 + n][j] = (hsum(acc[c][n]) + bi) * s.maskf[n0 + n];
    }
    __syncthreads();

    // ---- pooled = max over rows of actA ----------------------------------------
    {
        float mv = s.actA[0][tid];
#pragma unroll
        for (int n = 1; n < NPTS; n++) mv = fmaxf(mv, s.actA[n][tid]);
        s.pooled[tid] = mv;
    }

    // ---- pvec = mlp_w0[:, 256:512] @ pooled (row-invariant half of mlp0) --------
    s.pvec[tid] = gemmvec(s, mlp_w0, 2 * HD, HD, &s.pooled[0]);

    // ================= L3: mlp0 x-half (K=256) actA -> actB, BN+relu ============
#pragma unroll
    for (int c = 0; c < 4; c++)
#pragma unroll
        for (int n = 0; n < 5; n++) acc[c][n] = 0ULL;
    gemm20<8>(s, mlp_w0, 2 * HD, 0, &s.actA[0][0], HD, acc, cg, n0);
#pragma unroll
    for (int c = 0; c < 4; c++) {
        int j = cg + 64 * c;
        float sc = mlp_g0[j] * BN_INV, bi = mlp_b0[j];
        float pv = s.pvec[j];
#pragma unroll
        for (int n = 0; n < 5; n++)
            s.actB[n0 + n][j] = fmaxf(fmaf(hsum(acc[c][n]) + pv, sc, bi), 0.0f);
    }

    // ================= L4: mlp1 (K=256) actB -> actA, BN+relu ===================
#pragma unroll
    for (int c = 0; c < 4; c++)
#pragma unroll
        for (int n = 0; n < 5; n++) acc[c][n] = 0ULL;
    gemm20<8>(s, mlp_w1, HD, 0, &s.actB[0][0], HD, acc, cg, n0);
#pragma unroll
    for (int c = 0; c < 4; c++) {
        int j = cg + 64 * c;
        float sc = mlp_g1[j] * BN_INV, bi = mlp_b1[j];
#pragma unroll
        for (int n = 0; n < 5; n++)
            s.actA[n0 + n][j] = fmaxf(fmaf(hsum(acc[c][n]), sc, bi), 0.0f);
    }

    // ================= L5: mlp2 (K=256) actA -> actB, +bias, *mask ==============
#pragma unroll
    for (int c = 0; c < 4; c++)
#pragma unroll
        for (int n = 0; n < 5; n++) acc[c][n] = 0ULL;
    gemm20<8>(s, mlp_w2, HD, 0, &s.actA[0][0], HD, acc, cg, n0);
#pragma unroll
    for (int c = 0; c < 4; c++) {
        int j = cg + 64 * c;
        float bi = mlp_bias2[j];
#pragma unroll
        for (int n = 0; n < 5; n++)
            s.actB[n0 + n][j] = (hsum(acc[c][n]) + bi) * s.maskf[n0 + n];
    }
    __syncthreads();

    // ---- buf = max over rows of actB ---------------------------------------------
    {
        float mv = s.actB[0][tid];
#pragma unroll
        for (int n = 1; n < NPTS; n++) mv = fmaxf(mv, s.actB[n][tid]);
        s.bufv[tid] = mv;
    }

    // ---- out0: vec = relu(buf @ W0^T + b0) -----------------------------------------
    {
        float y = gemmvec(s, out_w0, HD, 0, &s.bufv[0]);
        s.vec[tid] = fmaxf(y + out_b0[tid], 0.0f);
    }

    // ---- out1: y = (vec @ W1^T + b1) * valid ---------------------------------------
    {
        float y = gemmvec(s, out_w1, HD, 0, &s.vec[0]);
        outp[(size_t)pl * HD + tid] = (y + out_b1[tid]) * s.validf;
    }
}

// ---------------- launch ----------------------------------------------------------
extern "C" void kernel_launch(void* const* d_in, const int* in_sizes, int n_in,
                              void* d_out, int out_size)
{
    const float* poly = (const float*)d_in[0];
    const void*  mask = d_in[1];

    detect_mask_mode_kernel<<<1, 256>>>((const unsigned char*)mask, in_sizes[1]);

    const int smem_bytes = (int)sizeof(Smem);
    cudaFuncSetAttribute(traj_encoder_kernel,
                         cudaFuncAttributeMaxDynamicSharedMemorySize, smem_bytes);

    traj_encoder_kernel<<<NPOLY, NTHR, smem_bytes>>>(
        poly, mask,
        (const float*)d_in[2],  (const float*)d_in[3],  (const float*)d_in[4],
        (const float*)d_in[5],  (const float*)d_in[6],  (const float*)d_in[7],
        (const float*)d_in[8],  (const float*)d_in[9],
        (const float*)d_in[10], (const float*)d_in[11], (const float*)d_in[12],
        (const float*)d_in[13], (const float*)d_in[14], (const float*)d_in[15],
        (const float*)d_in[16], (const float*)d_in[17],
        (const float*)d_in[18], (const float*)d_in[19],
        (const float*)d_in[20], (const float*)d_in[21],
        (float*)d_out);
}

// round 17
// speedup vs baseline: 1.6392x; 1.1481x over previous
#include <cuda_runtime.h>
#include <cuda_bf16.h>
#include <cstdint>

// ---------------------------------------------------------------------------
// TrajectoryEncoder fused kernel, v3.
// 2 polylines per CTA (4096 CTAs x 256 threads). fp32 math via fma.rn.f32x2.
// Thread (cg = tid&31, n0 = (tid>>5)*5) computes 8 strided columns
// (j = cg + 32c) x 5 rows. Weight tiles double-buffered in smem via
// cp.async.cg; 36-float row stride keeps STS/LDS conflict-free. The pooled
// half of mlp0 is factored into a per-polyline vector GEMM (pvec).
// ---------------------------------------------------------------------------

#define NPTS   20
#define CPL    2            // polylines per CTA
#define ROWS   (NPTS*CPL)   // 40
#define CIN    32
#define HD     256
#define KT     32           // k-tile width
#define WSTR   36           // padded tile row stride (floats) = 9 x 16B units
#define NPOLY  8192
#define NTHR   256

__device__ int g_mask_mode;   // 0=u8, 1=i32, 2=f32, 3=bf16

typedef unsigned long long ull;

// ---------------- packed fp32x2 helpers -------------------------------------
static __device__ __forceinline__ ull fma2(ull a, ull b, ull c) {
    ull d;
    asm("fma.rn.f32x2 %0, %1, %2, %3;" : "=l"(d) : "l"(a), "l"(b), "l"(c));
    return d;
}
static __device__ __forceinline__ float hsum(ull v) {
    float lo, hi;
    asm("mov.b64 {%0, %1}, %2;" : "=f"(lo), "=f"(hi) : "l"(v));
    return lo + hi;
}

// ---------------- cp.async helpers -------------------------------------------
static __device__ __forceinline__ uint32_t smem_u32(const void* p) {
    return (uint32_t)__cvta_generic_to_shared(p);
}
#define CP_ASYNC16(d, s) \
    asm volatile("cp.async.cg.shared.global [%0], [%1], 16;" :: "r"(d), "l"(s))
#define CP_COMMIT() asm volatile("cp.async.commit_group;")
#define CP_WAIT1()  asm volatile("cp.async.wait_group 1;")
#define CP_WAIT0()  asm volatile("cp.async.wait_group 0;")

// ---------------- shared memory layout ----------------------------------------
struct __align__(16) Smem {
    float Wt[2][HD * WSTR];    // double-buffered weight tile
    float in0[ROWS][CIN];
    float actA[ROWS][HD];
    float actB[ROWS][HD];
    float pooled[CPL][HD];
    float pvec[CPL][HD];
    float bufv[CPL][HD];
    float vec[CPL][HD];
    float maskf[ROWS];
    float validf[CPL];
};

// ---------------- weight tile staging (async) ----------------------------------
static __device__ __forceinline__ void stage_cp(
    float* __restrict__ dst, const float* __restrict__ Wg, int ldw, int k0)
{
    const int tid = threadIdx.x;
    const int jr  = tid >> 3;          // 0..31
    const int kk  = (tid & 7) * 4;     // 0..28
#pragma unroll
    for (int it = 0; it < 8; it++) {
        int j = it * 32 + jr;
        uint32_t d = smem_u32(dst + j * WSTR + kk);
        const float* sp = Wg + (size_t)j * ldw + k0 + kk;
        CP_ASYNC16(d, sp);
    }
}

// ---------------- main GEMM: 8 cols x 5 rows per thread --------------------------
template <int NT>
static __device__ __forceinline__ void gemm40(
    Smem& s, const float* __restrict__ Wg, int ldw, int k0off,
    const float* __restrict__ src, int rs,
    ull acc[8][5], int cg, int n0)
{
#pragma unroll
    for (int c = 0; c < 8; c++)
#pragma unroll
        for (int n = 0; n < 5; n++) acc[c][n] = 0ULL;

    stage_cp(s.Wt[0], Wg, ldw, k0off);
    CP_COMMIT();

#pragma unroll 1
    for (int t = 0; t < NT; t++) {
        if (t + 1 < NT) {
            stage_cp(s.Wt[(t + 1) & 1], Wg, ldw, k0off + (t + 1) * KT);
            CP_COMMIT();
            CP_WAIT1();
        } else {
            CP_WAIT0();
        }
        __syncthreads();

        const float* __restrict__ Wtb = s.Wt[t & 1];
        const float* __restrict__ sp  = src + t * KT;

#pragma unroll
        for (int kq = 0; kq < KT / 4; kq++) {
            ulonglong2 w[8];
#pragma unroll
            for (int c = 0; c < 8; c++)
                w[c] = *reinterpret_cast<const ulonglong2*>(
                    &Wtb[(cg + 32 * c) * WSTR + 4 * kq]);
#pragma unroll
            for (int n = 0; n < 5; n++) {
                ulonglong2 iv = *reinterpret_cast<const ulonglong2*>(
                    sp + (n0 + n) * rs + 4 * kq);
#pragma unroll
                for (int c = 0; c < 8; c++) {
                    acc[c][n] = fma2(w[c].x, iv.x, acc[c][n]);
                    acc[c][n] = fma2(w[c].y, iv.y, acc[c][n]);
                }
            }
        }
        __syncthreads();
    }
}

// ---------------- vector GEMM: 2 rows (one per polyline), col = tid ---------------
// y[p] = sum_k Wg[tid*ldw + k0off + k] * src[p*256 + k]
static __device__ __forceinline__ void gemmvec2(
    Smem& s, const float* __restrict__ Wg, int ldw, int k0off,
    const float* __restrict__ src, float y[2])
{
    const int tid = threadIdx.x;
    ull a0[2] = {0ULL, 0ULL}, a1[2] = {0ULL, 0ULL};

    stage_cp(s.Wt[0], Wg, ldw, k0off);
    CP_COMMIT();

#pragma unroll 1
    for (int t = 0; t < 8; t++) {
        if (t + 1 < 8) {
            stage_cp(s.Wt[(t + 1) & 1], Wg, ldw, k0off + (t + 1) * KT);
            CP_COMMIT();
            CP_WAIT1();
        } else {
            CP_WAIT0();
        }
        __syncthreads();

        const float* __restrict__ Wtb = s.Wt[t & 1];
        const float* __restrict__ sp  = src + t * KT;
#pragma unroll
        for (int kq = 0; kq < KT / 4; kq++) {
            ulonglong2 w  = *reinterpret_cast<const ulonglong2*>(&Wtb[tid * WSTR + 4 * kq]);
            ulonglong2 i0 = *reinterpret_cast<const ulonglong2*>(sp + 4 * kq);
            ulonglong2 i1 = *reinterpret_cast<const ulonglong2*>(sp + HD + 4 * kq);
            a0[0] = fma2(w.x, i0.x, a0[0]);
            a1[0] = fma2(w.y, i0.y, a1[0]);
            a0[1] = fma2(w.x, i1.x, a0[1]);
            a1[1] = fma2(w.y, i1.y, a1[1]);
        }
        __syncthreads();
    }
    y[0] = hsum(a0[0]) + hsum(a1[0]);
    y[1] = hsum(a0[1]) + hsum(a1[1]);
}

// ---------------- mask dtype sniffing ------------------------------------------
__global__ void detect_mask_mode_kernel(const unsigned char* __restrict__ m, int nelem)
{
    __shared__ int nz[4];
    __shared__ int mx;
    int t = threadIdx.x;
    if (t < 4) nz[t] = 0;
    if (t == 0) mx = 0;
    __syncthreads();

    int l0 = 0, l1 = 0, l2 = 0, l3 = 0, lm = 0;
    for (int i = t; i < nelem; i += blockDim.x) {
        int v = m[i];
        if (v) {
            int o = i & 3;
            l0 |= (o == 0); l1 |= (o == 1); l2 |= (o == 2); l3 |= (o == 3);
            if (v > lm) lm = v;
        }
    }
    if (l0) atomicOr(&nz[0], 1);
    if (l1) atomicOr(&nz[1], 1);
    if (l2) atomicOr(&nz[2], 1);
    if (l3) atomicOr(&nz[3], 1);
    atomicMax(&mx, lm);
    __syncthreads();

    if (t == 0) {
        int mode;
        if (nz[1])               mode = (mx > 1) ? 3 : 0;   // bf16 vs u8 0/1
        else if (nz[2] || nz[3]) mode = 2;                  // f32
        else if (nz[0])          mode = (mx > 1) ? 0 : 1;   // u8 vs i32
        else                     mode = 0;
        g_mask_mode = mode;
    }
}

// ---------------- main fused kernel ----------------------------------------------
__global__ void __launch_bounds__(NTHR, 1)
traj_encoder_kernel(
    const float* __restrict__ poly,
    const void*  __restrict__ maskp,
    const float* __restrict__ pre_w0,  const float* __restrict__ pre_g0,  const float* __restrict__ pre_b0,
    const float* __restrict__ pre_w1,  const float* __restrict__ pre_g1,  const float* __restrict__ pre_b1,
    const float* __restrict__ pre_w2,  const float* __restrict__ pre_bias2,
    const float* __restrict__ mlp_w0,  const float* __restrict__ mlp_g0,  const float* __restrict__ mlp_b0,
    const float* __restrict__ mlp_w1,  const float* __restrict__ mlp_g1,  const float* __restrict__ mlp_b1,
    const float* __restrict__ mlp_w2,  const float* __restrict__ mlp_bias2,
    const float* __restrict__ out_w0,  const float* __restrict__ out_b0,
    const float* __restrict__ out_w1,  const float* __restrict__ out_b1,
    float* __restrict__ outp)
{
    extern __shared__ unsigned char smem_raw[];
    Smem& s = *reinterpret_cast<Smem*>(smem_raw);

    const int tid = threadIdx.x;
    const int cg  = tid & 31;          // cols j = cg + 32c, c=0..7
    const int n0  = (tid >> 5) * 5;    // rows n0..n0+4 (rowgroup == warp)
    const int pg  = (n0 >= NPTS);      // polyline index of this thread's rows
    const int pl0 = blockIdx.x * CPL;
    const float BN_INV = 0.99999500003749969f;   // 1/sqrt(1+1e-5)
    const int mmode = g_mask_mode;

    // ---- load points + mask -------------------------------------------------
    {
        const float4* pin = reinterpret_cast<const float4*>(poly + (size_t)pl0 * (NPTS * CIN));
        float4* din = reinterpret_cast<float4*>(&s.in0[0][0]);
#pragma unroll
        for (int i = tid; i < ROWS * CIN / 4; i += NTHR)
            din[i] = pin[i];
    }
    if (tid < ROWS) {
        const int gi = pl0 * NPTS + tid;
        bool mv;
        switch (mmode) {
            case 1:  mv = ((const int*)maskp)[gi] != 0;                                  break;
            case 2:  mv = ((const float*)maskp)[gi] != 0.0f;                             break;
            case 3:  mv = __bfloat162float(((const __nv_bfloat16*)maskp)[gi]) != 0.0f;   break;
            default: mv = ((const unsigned char*)maskp)[gi] != 0;                        break;
        }
        s.maskf[tid] = mv ? 1.0f : 0.0f;
    }
    __syncthreads();
    if (tid < CPL) {
        float v = 0.0f;
        for (int n = 0; n < NPTS; n++) v = fmaxf(v, s.maskf[tid * NPTS + n]);
        s.validf[tid] = v;
    }
    // visibility covered by gemm40's internal syncs

    ull acc[8][5];

    // ================= L0: pre0 (K=32) in0 -> actA, BN+relu =====================
    gemm40<1>(s, pre_w0, CIN, 0, &s.in0[0][0], CIN, acc, cg, n0);
#pragma unroll
    for (int c = 0; c < 8; c++) {
        int j = cg + 32 * c;
        float sc = pre_g0[j] * BN_INV, bi = pre_b0[j];
#pragma unroll
        for (int n = 0; n < 5; n++)
            s.actA[n0 + n][j] = fmaxf(fmaf(hsum(acc[c][n]), sc, bi), 0.0f);
    }

    // ================= L1: pre1 (K=256) actA -> actB, BN+relu ===================
    gemm40<8>(s, pre_w1, HD, 0, &s.actA[0][0], HD, acc, cg, n0);
#pragma unroll
    for (int c = 0; c < 8; c++) {
        int j = cg + 32 * c;
        float sc = pre_g1[j] * BN_INV, bi = pre_b1[j];
#pragma unroll
        for (int n = 0; n < 5; n++)
            s.actB[n0 + n][j] = fmaxf(fmaf(hsum(acc[c][n]), sc, bi), 0.0f);
    }

    // ================= L2: pre2 (K=256) actB -> actA, +bias, *mask ==============
    gemm40<8>(s, pre_w2, HD, 0, &s.actB[0][0], HD, acc, cg, n0);
#pragma unroll
    for (int c = 0; c < 8; c++) {
        int j = cg + 32 * c;
        float bi = pre_bias2[j];
#pragma unroll
        for (int n = 0; n < 5; n++)
            s.actA[n0 + n][j] = (hsum(acc[c][n]) + bi) * s.maskf[n0 + n];
    }
    __syncthreads();

    // ---- pooled[p] = max over rows of actA -------------------------------------
#pragma unroll
    for (int p = 0; p < CPL; p++) {
        float mv = s.actA[p * NPTS][tid];
#pragma unroll
        for (int n = 1; n < NPTS; n++) mv = fmaxf(mv, s.actA[p * NPTS + n][tid]);
        s.pooled[p][tid] = mv;
    }

    // ---- pvec[p] = mlp_w0[:, 256:512] @ pooled[p] --------------------------------
    {
        float y[2];
        gemmvec2(s, mlp_w0, 2 * HD, HD, &s.pooled[0][0], y);
        s.pvec[0][tid] = y[0];
        s.pvec[1][tid] = y[1];
    }

    // ================= L3: mlp0 x-half (K=256) actA -> actB, BN+relu ============
    gemm40<8>(s, mlp_w0, 2 * HD, 0, &s.actA[0][0], HD, acc, cg, n0);
#pragma unroll
    for (int c = 0; c < 8; c++) {
        int j = cg + 32 * c;
        float sc = mlp_g0[j] * BN_INV, bi = mlp_b0[j];
        float pv = s.pvec[pg][j];
#pragma unroll
        for (int n = 0; n < 5; n++)
            s.actB[n0 + n][j] = fmaxf(fmaf(hsum(acc[c][n]) + pv, sc, bi), 0.0f);
    }

    // ================= L4: mlp1 (K=256) actB -> actA, BN+relu ===================
    gemm40<8>(s, mlp_w1, HD, 0, &s.actB[0][0], HD, acc, cg, n0);
#pragma unroll
    for (int c = 0; c < 8; c++) {
        int j = cg + 32 * c;
        float sc = mlp_g1[j] * BN_INV, bi = mlp_b1[j];
#pragma unroll
        for (int n = 0; n < 5; n++)
            s.actA[n0 + n][j] = fmaxf(fmaf(hsum(acc[c][n]), sc, bi), 0.0f);
    }

    // ================= L5: mlp2 (K=256) actA -> actB, +bias, *mask ==============
    gemm40<8>(s, mlp_w2, HD, 0, &s.actA[0][0], HD, acc, cg, n0);
#pragma unroll
    for (int c = 0; c < 8; c++) {
        int j = cg + 32 * c;
        float bi = mlp_bias2[j];
#pragma unroll
        for (int n = 0; n < 5; n++)
            s.actB[n0 + n][j] = (hsum(acc[c][n]) + bi) * s.maskf[n0 + n];
    }
    __syncthreads();

    // ---- bufv[p] = max over rows of actB -----------------------------------------
#pragma unroll
    for (int p = 0; p < CPL; p++) {
        float mv = s.actB[p * NPTS][tid];
#pragma unroll
        for (int n = 1; n < NPTS; n++) mv = fmaxf(mv, s.actB[p * NPTS + n][tid]);
        s.bufv[p][tid] = mv;
    }

    // ---- out0: vec[p] = relu(bufv[p] @ W0^T + b0) ----------------------------------
    {
        float y[2];
        gemmvec2(s, out_w0, HD, 0, &s.bufv[0][0], y);
        float bi = out_b0[tid];
        s.vec[0][tid] = fmaxf(y[0] + bi, 0.0f);
        s.vec[1][tid] = fmaxf(y[1] + bi, 0.0f);
    }

    // ---- out1: y[p] = (vec[p] @ W1^T + b1) * valid[p] --------------------------------
    {
        float y[2];
        gemmvec2(s, out_w1, HD, 0, &s.vec[0][0], y);
        float bi = out_b1[tid];
        outp[(size_t)(pl0 + 0) * HD + tid] = (y[0] + bi) * s.validf[0];
        outp[(size_t)(pl0 + 1) * HD + tid] = (y[1] + bi) * s.validf[1];
    }
}

// ---------------- launch ------------------------------------------------------------
extern "C" void kernel_launch(void* const* d_in, const int* in_sizes, int n_in,
                              void* d_out, int out_size)
{
    const float* poly = (const float*)d_in[0];
    const void*  mask = d_in[1];

    detect_mask_mode_kernel<<<1, 256>>>((const unsigned char*)mask, in_sizes[1]);

    const int smem_bytes = (int)sizeof(Smem);
    cudaFuncSetAttribute(traj_encoder_kernel,
                         cudaFuncAttributeMaxDynamicSharedMemorySize, smem_bytes);

    traj_encoder_kernel<<<NPOLY / CPL, NTHR, smem_bytes>>>(
        poly, mask,
        (const float*)d_in[2],  (const float*)d_in[3],  (const float*)d_in[4],
        (const float*)d_in[5],  (const float*)d_in[6],  (const float*)d_in[7],
        (const float*)d_in[8],  (const float*)d_in[9],
        (const float*)d_in[10], (const float*)d_in[11], (const float*)d_in[12],
        (const float*)d_in[13], (const float*)d_in[14], (const float*)d_in[15],
        (const float*)d_in[16], (const float*)d_in[17],
        (const float*)d_in[18], (const float*)d_in[19],
        (const float*)d_in[20], (const float*)d_in[21],
        (float*)d_out);
}